// round 1
// baseline (speedup 1.0000x reference)
#include <cuda_runtime.h>
#include <math.h>

#define BB 8
#define CC 256
#define HWN 4096
#define RR 16
#define MQKV 288   // 256 v rows + 16 q rows + 16 k rows

// ---------------- scratch (device globals; no allocations) ----------------
__device__ float g_avg[BB*CC];
__device__ float g_mx [BB*CC];
__device__ float g_gate[BB*CC];
__device__ float g_xg[(size_t)BB*CC*HWN];           // 33.5 MB  gated input
__device__ float g_wcat[MQKV*CC];                   // packed [v;q;k] weights
__device__ float g_bcat[MQKV];
__device__ float g_q[BB*RR*HWN];
__device__ float g_k[BB*RR*HWN];
__device__ float g_v[(size_t)BB*CC*HWN];            // 33.5 MB
__device__ float g_E[134217728];                    // 512 MB  exp(S) unnormalized
__device__ float g_inv[BB*HWN];                     // 1/rowsum

// ---------------- 1) avg+max pool over HW per (b,c) ----------------
__global__ __launch_bounds__(256) void k_pool(const float* __restrict__ x) {
    int bc = blockIdx.x;
    const float4* p = (const float4*)(x + (size_t)bc * HWN);
    float s = 0.f, m = -1e30f;
    for (int i = threadIdx.x; i < HWN/4; i += 256) {
        float4 v = p[i];
        s += v.x + v.y + v.z + v.w;
        m = fmaxf(m, fmaxf(fmaxf(v.x, v.y), fmaxf(v.z, v.w)));
    }
    __shared__ float ss[8], sm[8];
    for (int o = 16; o; o >>= 1) {
        s += __shfl_xor_sync(0xffffffffu, s, o);
        m = fmaxf(m, __shfl_xor_sync(0xffffffffu, m, o));
    }
    if ((threadIdx.x & 31) == 0) { ss[threadIdx.x >> 5] = s; sm[threadIdx.x >> 5] = m; }
    __syncthreads();
    if (threadIdx.x == 0) {
        float S = 0.f, M = -1e30f;
        for (int w = 0; w < 8; w++) { S += ss[w]; M = fmaxf(M, sm[w]); }
        g_avg[bc] = S * (1.f / HWN);
        g_mx[bc]  = M;
    }
}

// ---------------- 2) SE gate: sigmoid(fc(avg)+fc(max)) ----------------
__global__ __launch_bounds__(256) void k_gate(const float* __restrict__ w1,
                                              const float* __restrict__ w2) {
    int b = blockIdx.x, t = threadIdx.x;
    __shared__ float sa[CC], sx[CC], h[RR];
    sa[t] = g_avg[b*CC + t];
    sx[t] = g_mx [b*CC + t];
    __syncthreads();
    if (t < RR) {
        float da = 0.f, dm = 0.f;
        const float* w = w1 + t*CC;
        for (int c = 0; c < CC; c++) { da += w[c]*sa[c]; dm += w[c]*sx[c]; }
        h[t] = fmaxf(da, 0.f) + fmaxf(dm, 0.f);   // relu(fc(avg)) + relu(fc(max))
    }
    __syncthreads();
    float g = 0.f;
    const float* w = w2 + t*RR;                   // ca_w2 is [C, R]
    #pragma unroll
    for (int r = 0; r < RR; r++) g += w[r]*h[r];
    g_gate[b*CC + t] = 1.f / (1.f + expf(-g));
}

// ---------------- 3) xg = x * gate ----------------
__global__ __launch_bounds__(256) void k_xg(const float* __restrict__ x) {
    size_t i = (size_t)blockIdx.x * 256 + threadIdx.x;       // float4 index
    int bc = (int)(i / (HWN/4));
    float g = g_gate[bc];
    float4 v = ((const float4*)x)[i];
    v.x *= g; v.y *= g; v.z *= g; v.w *= g;
    ((float4*)g_xg)[i] = v;
}

// ---------------- 4) pack [v_w; q_w; k_w] and biases ----------------
__global__ __launch_bounds__(256) void k_wpack(const float* __restrict__ vw,
                                               const float* __restrict__ qw,
                                               const float* __restrict__ kw,
                                               const float* __restrict__ vb,
                                               const float* __restrict__ qb,
                                               const float* __restrict__ kb) {
    int o = blockIdx.x, t = threadIdx.x;
    const float* src; float bias;
    if (o < CC)            { src = vw + o*CC;           bias = vb[o]; }
    else if (o < CC + RR)  { src = qw + (o-CC)*CC;      bias = qb[o-CC]; }
    else                   { src = kw + (o-CC-RR)*CC;   bias = kb[o-CC-RR]; }
    g_wcat[o*CC + t] = src[t];
    if (t == 0) g_bcat[o] = bias;
}

// ---------------- 5) fused QKV projection GEMM: [288 x 256] @ xg[b][256 x 4096] ----------------
// tile 128x128, Kc=16, 256 threads, 8x8 microtile
__global__ __launch_bounds__(256) void k_qkv() {
    int b  = blockIdx.z;
    int o0 = blockIdx.y * 128;
    int n0 = blockIdx.x * 128;
    __shared__ float As[16][132];
    __shared__ float Bs[16][132];
    int tid = threadIdx.x;
    int tx = tid & 15, ty = tid >> 4;
    float acc[8][8];
    #pragma unroll
    for (int i = 0; i < 8; i++)
        #pragma unroll
        for (int j = 0; j < 8; j++) acc[i][j] = 0.f;

    const float* Bbase = g_xg + (size_t)b * CC * HWN;
    for (int k0 = 0; k0 < CC; k0 += 16) {
        #pragma unroll
        for (int l = 0; l < 2; l++) {
            int e = tid + l*256;          // 0..511 float4 id
            int row = e >> 2, col4 = e & 3;
            int o = o0 + row;
            float4 v = (o < MQKV) ? *(const float4*)(g_wcat + o*CC + k0 + col4*4)
                                  : make_float4(0.f, 0.f, 0.f, 0.f);
            As[col4*4+0][row] = v.x; As[col4*4+1][row] = v.y;
            As[col4*4+2][row] = v.z; As[col4*4+3][row] = v.w;
        }
        #pragma unroll
        for (int l = 0; l < 2; l++) {
            int e = tid + l*256;
            int kk = e >> 5, n4 = e & 31;
            *(float4*)&Bs[kk][n4*4] = *(const float4*)(Bbase + (size_t)(k0+kk)*HWN + n0 + n4*4);
        }
        __syncthreads();
        #pragma unroll
        for (int kk = 0; kk < 16; kk++) {
            float a[8], bb[8];
            *(float4*)(a)    = *(float4*)&As[kk][ty*8];
            *(float4*)(a+4)  = *(float4*)&As[kk][ty*8+4];
            *(float4*)(bb)   = *(float4*)&Bs[kk][tx*8];
            *(float4*)(bb+4) = *(float4*)&Bs[kk][tx*8+4];
            #pragma unroll
            for (int i = 0; i < 8; i++)
                #pragma unroll
                for (int j = 0; j < 8; j++) acc[i][j] += a[i]*bb[j];
        }
        __syncthreads();
    }
    #pragma unroll
    for (int i = 0; i < 8; i++) {
        int o = o0 + ty*8 + i;
        if (o >= MQKV) continue;
        float bias = g_bcat[o];
        float* dst;
        if (o < CC)           dst = g_v + ((size_t)(b*CC + o)) * HWN;
        else if (o < CC + RR) dst = g_q + ((size_t)(b*RR + (o-CC))) * HWN;
        else                  dst = g_k + ((size_t)(b*RR + (o-CC-RR))) * HWN;
        #pragma unroll
        for (int j = 0; j < 8; j += 4) {
            float4 v;
            v.x = acc[i][j+0] + bias; v.y = acc[i][j+1] + bias;
            v.z = acc[i][j+2] + bias; v.w = acc[i][j+3] + bias;
            *(float4*)(dst + n0 + tx*8 + j) = v;
        }
    }
}

// ---------------- 6) scores + exp: E[b,i,j] = exp(sum_r q[r,i]*k[r,j]) ----------------
__global__ __launch_bounds__(256) void k_scores() {
    int b  = blockIdx.z;
    int i0 = blockIdx.y * 128;
    int j0 = blockIdx.x * 128;
    __shared__ float Qs[16][132];
    __shared__ float Ks[16][132];
    int tid = threadIdx.x;
    int tx = tid & 15, ty = tid >> 4;
    #pragma unroll
    for (int l = 0; l < 2; l++) {
        int e = tid + l*256;
        int r = e >> 5, n4 = e & 31;
        *(float4*)&Qs[r][n4*4] = *(const float4*)(g_q + (size_t)(b*RR + r)*HWN + i0 + n4*4);
        *(float4*)&Ks[r][n4*4] = *(const float4*)(g_k + (size_t)(b*RR + r)*HWN + j0 + n4*4);
    }
    __syncthreads();
    float acc[8][8];
    #pragma unroll
    for (int i = 0; i < 8; i++)
        #pragma unroll
        for (int j = 0; j < 8; j++) acc[i][j] = 0.f;
    #pragma unroll
    for (int r = 0; r < 16; r++) {
        float a[8], bb[8];
        *(float4*)(a)    = *(float4*)&Qs[r][ty*8];
        *(float4*)(a+4)  = *(float4*)&Qs[r][ty*8+4];
        *(float4*)(bb)   = *(float4*)&Ks[r][tx*8];
        *(float4*)(bb+4) = *(float4*)&Ks[r][tx*8+4];
        #pragma unroll
        for (int i = 0; i < 8; i++)
            #pragma unroll
            for (int j = 0; j < 8; j++) acc[i][j] += a[i]*bb[j];
    }
    #pragma unroll
    for (int i = 0; i < 8; i++) {
        float* dst = g_E + ((size_t)(b*HWN + i0 + ty*8 + i)) * HWN + j0 + tx*8;
        #pragma unroll
        for (int j = 0; j < 8; j += 4) {
            float4 v;
            v.x = expf(acc[i][j+0]); v.y = expf(acc[i][j+1]);
            v.z = expf(acc[i][j+2]); v.w = expf(acc[i][j+3]);
            *(float4*)(dst + j) = v;
        }
    }
}

// ---------------- 7) row sums -> 1/sum ----------------
__global__ __launch_bounds__(256) void k_rowsum() {
    size_t row = blockIdx.x;
    const float4* p = (const float4*)(g_E + row * HWN);
    float s = 0.f;
    for (int i = threadIdx.x; i < HWN/4; i += 256) {
        float4 v = p[i];
        s += v.x + v.y + v.z + v.w;
    }
    __shared__ float ss[8];
    for (int o = 16; o; o >>= 1) s += __shfl_xor_sync(0xffffffffu, s, o);
    if ((threadIdx.x & 31) == 0) ss[threadIdx.x >> 5] = s;
    __syncthreads();
    if (threadIdx.x == 0) {
        float S = 0.f;
        for (int w = 0; w < 8; w++) S += ss[w];
        g_inv[row] = 1.f / S;
    }
}

// ---------------- 8) AV GEMM + epilogue: out = gamma * (V @ E^T)*inv + xg ----------------
// Out[c][i] = sum_j V[c][j] * E[i][j];  tile 128x128 (c x i), Kc=16, 8x8 micro
__global__ __launch_bounds__(256) void k_av(const float* __restrict__ gamma,
                                            float* __restrict__ out) {
    int b  = blockIdx.z;
    int c0 = blockIdx.y * 128;
    int i0 = blockIdx.x * 128;
    __shared__ float As[16][132];   // As[kk][c]
    __shared__ float Bs[16][132];   // Bs[kk][i]
    int tid = threadIdx.x;
    int tx = tid & 15, ty = tid >> 4;
    float acc[8][8];
    #pragma unroll
    for (int i = 0; i < 8; i++)
        #pragma unroll
        for (int j = 0; j < 8; j++) acc[i][j] = 0.f;

    const float* Vb = g_v + (size_t)b * CC * HWN;
    const float* Eb = g_E + (size_t)b * HWN * HWN;

    for (int k0 = 0; k0 < HWN; k0 += 16) {
        #pragma unroll
        for (int l = 0; l < 2; l++) {
            int e = tid + l*256;
            int row = e >> 2, col4 = e & 3;
            float4 v = *(const float4*)(Vb + (size_t)(c0+row)*HWN + k0 + col4*4);
            As[col4*4+0][row] = v.x; As[col4*4+1][row] = v.y;
            As[col4*4+2][row] = v.z; As[col4*4+3][row] = v.w;
        }
        #pragma unroll
        for (int l = 0; l < 2; l++) {
            int e = tid + l*256;
            int row = e >> 2, col4 = e & 3;
            float4 v = *(const float4*)(Eb + (size_t)(i0+row)*HWN + k0 + col4*4);
            Bs[col4*4+0][row] = v.x; Bs[col4*4+1][row] = v.y;
            Bs[col4*4+2][row] = v.z; Bs[col4*4+3][row] = v.w;
        }
        __syncthreads();
        #pragma unroll
        for (int kk = 0; kk < 16; kk++) {
            float a[8], bb[8];
            *(float4*)(a)    = *(float4*)&As[kk][ty*8];
            *(float4*)(a+4)  = *(float4*)&As[kk][ty*8+4];
            *(float4*)(bb)   = *(float4*)&Bs[kk][tx*8];
            *(float4*)(bb+4) = *(float4*)&Bs[kk][tx*8+4];
            #pragma unroll
            for (int i = 0; i < 8; i++)
                #pragma unroll
                for (int j = 0; j < 8; j++) acc[i][j] += a[i]*bb[j];
        }
        __syncthreads();
    }

    float gm = gamma[0];
    float inv[8];
    #pragma unroll
    for (int j = 0; j < 8; j++) inv[j] = g_inv[b*HWN + i0 + tx*8 + j];
    #pragma unroll
    for (int i = 0; i < 8; i++) {
        size_t base = ((size_t)(b*CC + c0 + ty*8 + i)) * HWN + i0 + tx*8;
        #pragma unroll
        for (int j = 0; j < 8; j += 4) {
            float4 xgv = *(const float4*)(g_xg + base + j);
            float4 v;
            v.x = gm * acc[i][j+0]*inv[j+0] + xgv.x;
            v.y = gm * acc[i][j+1]*inv[j+1] + xgv.y;
            v.z = gm * acc[i][j+2]*inv[j+2] + xgv.z;
            v.w = gm * acc[i][j+3]*inv[j+3] + xgv.w;
            *(float4*)(out + base + j) = v;
        }
    }
}

// ---------------- launch ----------------
extern "C" void kernel_launch(void* const* d_in, const int* in_sizes, int n_in,
                              void* d_out, int out_size) {
    const float* x     = (const float*)d_in[0];
    const float* ca_w1 = (const float*)d_in[1];
    const float* ca_w2 = (const float*)d_in[2];
    const float* q_w   = (const float*)d_in[3];
    const float* q_b   = (const float*)d_in[4];
    const float* k_w   = (const float*)d_in[5];
    const float* k_b   = (const float*)d_in[6];
    const float* v_w   = (const float*)d_in[7];
    const float* v_b   = (const float*)d_in[8];
    const float* gamma = (const float*)d_in[9];
    float* out = (float*)d_out;

    k_pool  <<<BB*CC, 256>>>(x);
    k_wpack <<<MQKV, 256>>>(v_w, q_w, k_w, v_b, q_b, k_b);
    k_gate  <<<BB, 256>>>(ca_w1, ca_w2);
    k_xg    <<<(BB*CC*HWN/4)/256, 256>>>(x);
    k_qkv   <<<dim3(HWN/128, 3, BB), 256>>>();
    k_scores<<<dim3(HWN/128, HWN/128, BB), 256>>>();
    k_rowsum<<<BB*HWN, 256>>>();
    k_av    <<<dim3(HWN/128, CC/128, BB), 256>>>(gamma, out);
}

// round 4
// speedup vs baseline: 3.2228x; 3.2228x over previous
#include <cuda_runtime.h>
#include <cuda_bf16.h>
#include <cstdint>
#include <math.h>

#define BB 8
#define CC 256
#define HWN 4096
#define RR 16
#define MQKV 288   // 256 v rows + 16 q rows + 16 k rows

// ---------------- scratch (device globals; no allocations) ----------------
__device__ float g_avg[BB*CC];
__device__ float g_mx [BB*CC];
__device__ float g_gate[BB*CC];
__device__ float g_xg[(size_t)BB*CC*HWN];           // 33.5 MB  gated input (fp32, residual + GEMM input)
__device__ float g_wcat[MQKV*CC];                   // packed [v;q;k] weights
__device__ float g_bcat[MQKV];
__device__ float g_q[BB*RR*HWN];
__device__ float g_k[BB*RR*HWN];
__device__ __nv_bfloat16 g_vh[(size_t)BB*CC*HWN];   // 16.7 MB  V in bf16
__device__ __nv_bfloat16 g_Eh[(size_t)134217728];   // 256 MB   exp(S) unnormalized, bf16
__device__ float g_inv[BB*HWN];                     // 1/rowsum

// ---------------- asm helpers ----------------
__device__ __forceinline__ unsigned int sptr(const void* p) {
    return (unsigned int)__cvta_generic_to_shared(p);
}
#define CP16(dst, src) asm volatile("cp.async.cg.shared.global [%0], [%1], 16;\n" :: "r"(sptr(dst)), "l"(src))
#define CP_COMMIT()    asm volatile("cp.async.commit_group;\n")
#define CP_WAIT(n)     asm volatile("cp.async.wait_group %0;\n" :: "n"(n))
#define LDSM4(r0,r1,r2,r3,addr) \
    asm volatile("ldmatrix.sync.aligned.m8n8.x4.shared.b16 {%0,%1,%2,%3}, [%4];\n" \
        : "=r"(r0),"=r"(r1),"=r"(r2),"=r"(r3) : "r"(addr))
#define MMA16816(d,a,b0,b1) \
    asm volatile("mma.sync.aligned.m16n8k16.row.col.f32.bf16.bf16.f32 " \
        "{%0,%1,%2,%3}, {%4,%5,%6,%7}, {%8,%9}, {%0,%1,%2,%3};\n" \
        : "+f"(d[0]),"+f"(d[1]),"+f"(d[2]),"+f"(d[3]) \
        : "r"(a[0]),"r"(a[1]),"r"(a[2]),"r"(a[3]), "r"(b0),"r"(b1))

// ---------------- 1) avg+max pool over HW per (b,c) ----------------
__global__ __launch_bounds__(256) void k_pool(const float* __restrict__ x) {
    int bc = blockIdx.x;
    const float4* p = (const float4*)(x + (size_t)bc * HWN);
    float s = 0.f, m = -1e30f;
    for (int i = threadIdx.x; i < HWN/4; i += 256) {
        float4 v = p[i];
        s += v.x + v.y + v.z + v.w;
        m = fmaxf(m, fmaxf(fmaxf(v.x, v.y), fmaxf(v.z, v.w)));
    }
    __shared__ float ss[8], sm[8];
    for (int o = 16; o; o >>= 1) {
        s += __shfl_xor_sync(0xffffffffu, s, o);
        m = fmaxf(m, __shfl_xor_sync(0xffffffffu, m, o));
    }
    if ((threadIdx.x & 31) == 0) { ss[threadIdx.x >> 5] = s; sm[threadIdx.x >> 5] = m; }
    __syncthreads();
    if (threadIdx.x == 0) {
        float S = 0.f, M = -1e30f;
        for (int w = 0; w < 8; w++) { S += ss[w]; M = fmaxf(M, sm[w]); }
        g_avg[bc] = S * (1.f / HWN);
        g_mx[bc]  = M;
    }
}

// ---------------- 2) SE gate: sigmoid(fc(avg)+fc(max)) ----------------
__global__ __launch_bounds__(256) void k_gate(const float* __restrict__ w1,
                                              const float* __restrict__ w2) {
    int b = blockIdx.x, t = threadIdx.x;
    __shared__ float sa[CC], sx[CC], h[RR];
    sa[t] = g_avg[b*CC + t];
    sx[t] = g_mx [b*CC + t];
    __syncthreads();
    if (t < RR) {
        float da = 0.f, dm = 0.f;
        const float* w = w1 + t*CC;
        for (int c = 0; c < CC; c++) { da += w[c]*sa[c]; dm += w[c]*sx[c]; }
        h[t] = fmaxf(da, 0.f) + fmaxf(dm, 0.f);
    }
    __syncthreads();
    float g = 0.f;
    const float* w = w2 + t*RR;
    #pragma unroll
    for (int r = 0; r < RR; r++) g += w[r]*h[r];
    g_gate[b*CC + t] = 1.f / (1.f + expf(-g));
}

// ---------------- 3) xg = x * gate ----------------
__global__ __launch_bounds__(256) void k_xg(const float* __restrict__ x) {
    size_t i = (size_t)blockIdx.x * 256 + threadIdx.x;       // float4 index
    int bc = (int)(i / (HWN/4));
    float g = g_gate[bc];
    float4 v = ((const float4*)x)[i];
    v.x *= g; v.y *= g; v.z *= g; v.w *= g;
    ((float4*)g_xg)[i] = v;
}

// ---------------- 4) pack [v_w; q_w; k_w] and biases ----------------
__global__ __launch_bounds__(256) void k_wpack(const float* __restrict__ vw,
                                               const float* __restrict__ qw,
                                               const float* __restrict__ kw,
                                               const float* __restrict__ vb,
                                               const float* __restrict__ qb,
                                               const float* __restrict__ kb) {
    int o = blockIdx.x, t = threadIdx.x;
    const float* src; float bias;
    if (o < CC)            { src = vw + o*CC;           bias = vb[o]; }
    else if (o < CC + RR)  { src = qw + (o-CC)*CC;      bias = qb[o-CC]; }
    else                   { src = kw + (o-CC-RR)*CC;   bias = kb[o-CC-RR]; }
    g_wcat[o*CC + t] = src[t];
    if (t == 0) g_bcat[o] = bias;
}

// ---------------- 5) fused QKV projection GEMM (fp32 FFMA, small) ----------------
__global__ __launch_bounds__(256) void k_qkv() {
    int b  = blockIdx.z;
    int o0 = blockIdx.y * 128;
    int n0 = blockIdx.x * 128;
    __shared__ float As[16][132];
    __shared__ float Bs[16][132];
    int tid = threadIdx.x;
    int tx = tid & 15, ty = tid >> 4;
    float acc[8][8];
    #pragma unroll
    for (int i = 0; i < 8; i++)
        #pragma unroll
        for (int j = 0; j < 8; j++) acc[i][j] = 0.f;

    const float* Bbase = g_xg + (size_t)b * CC * HWN;
    for (int k0 = 0; k0 < CC; k0 += 16) {
        #pragma unroll
        for (int l = 0; l < 2; l++) {
            int e = tid + l*256;
            int row = e >> 2, col4 = e & 3;
            int o = o0 + row;
            float4 v = (o < MQKV) ? *(const float4*)(g_wcat + o*CC + k0 + col4*4)
                                  : make_float4(0.f, 0.f, 0.f, 0.f);
            As[col4*4+0][row] = v.x; As[col4*4+1][row] = v.y;
            As[col4*4+2][row] = v.z; As[col4*4+3][row] = v.w;
        }
        #pragma unroll
        for (int l = 0; l < 2; l++) {
            int e = tid + l*256;
            int kk = e >> 5, n4 = e & 31;
            *(float4*)&Bs[kk][n4*4] = *(const float4*)(Bbase + (size_t)(k0+kk)*HWN + n0 + n4*4);
        }
        __syncthreads();
        #pragma unroll
        for (int kk = 0; kk < 16; kk++) {
            float a[8], bb[8];
            *(float4*)(a)    = *(float4*)&As[kk][ty*8];
            *(float4*)(a+4)  = *(float4*)&As[kk][ty*8+4];
            *(float4*)(bb)   = *(float4*)&Bs[kk][tx*8];
            *(float4*)(bb+4) = *(float4*)&Bs[kk][tx*8+4];
            #pragma unroll
            for (int i = 0; i < 8; i++)
                #pragma unroll
                for (int j = 0; j < 8; j++) acc[i][j] += a[i]*bb[j];
        }
        __syncthreads();
    }
    #pragma unroll
    for (int i = 0; i < 8; i++) {
        int o = o0 + ty*8 + i;
        if (o >= MQKV) continue;
        float bias = g_bcat[o];
        if (o < CC) {
            // V goes out as bf16
            __nv_bfloat16* dst = g_vh + ((size_t)(b*CC + o)) * HWN + n0 + tx*8;
            #pragma unroll
            for (int j = 0; j < 8; j += 2) {
                *(__nv_bfloat162*)(dst + j) =
                    __floats2bfloat162_rn(acc[i][j+0] + bias, acc[i][j+1] + bias);
            }
        } else {
            float* dst = (o < CC + RR)
                ? g_q + ((size_t)(b*RR + (o-CC))) * HWN
                : g_k + ((size_t)(b*RR + (o-CC-RR))) * HWN;
            #pragma unroll
            for (int j = 0; j < 8; j += 4) {
                float4 v;
                v.x = acc[i][j+0] + bias; v.y = acc[i][j+1] + bias;
                v.z = acc[i][j+2] + bias; v.w = acc[i][j+3] + bias;
                *(float4*)(dst + n0 + tx*8 + j) = v;
            }
        }
    }
}

// ---------------- 6) scores + exp -> bf16 E ----------------
__global__ __launch_bounds__(256) void k_scores() {
    int b  = blockIdx.z;
    int i0 = blockIdx.y * 128;
    int j0 = blockIdx.x * 128;
    __shared__ float Qs[16][132];
    __shared__ float Ks[16][132];
    int tid = threadIdx.x;
    int tx = tid & 15, ty = tid >> 4;
    #pragma unroll
    for (int l = 0; l < 2; l++) {
        int e = tid + l*256;
        int r = e >> 5, n4 = e & 31;
        *(float4*)&Qs[r][n4*4] = *(const float4*)(g_q + (size_t)(b*RR + r)*HWN + i0 + n4*4);
        *(float4*)&Ks[r][n4*4] = *(const float4*)(g_k + (size_t)(b*RR + r)*HWN + j0 + n4*4);
    }
    __syncthreads();
    float acc[8][8];
    #pragma unroll
    for (int i = 0; i < 8; i++)
        #pragma unroll
        for (int j = 0; j < 8; j++) acc[i][j] = 0.f;
    #pragma unroll
    for (int r = 0; r < 16; r++) {
        float a[8], bb[8];
        *(float4*)(a)    = *(float4*)&Qs[r][ty*8];
        *(float4*)(a+4)  = *(float4*)&Qs[r][ty*8+4];
        *(float4*)(bb)   = *(float4*)&Ks[r][tx*8];
        *(float4*)(bb+4) = *(float4*)&Ks[r][tx*8+4];
        #pragma unroll
        for (int i = 0; i < 8; i++)
            #pragma unroll
            for (int j = 0; j < 8; j++) acc[i][j] += a[i]*bb[j];
    }
    #pragma unroll
    for (int i = 0; i < 8; i++) {
        __nv_bfloat16* dst = g_Eh + ((size_t)(b*HWN + i0 + ty*8 + i)) * HWN + j0 + tx*8;
        union { __nv_bfloat162 h[4]; uint4 u; } pk;
        #pragma unroll
        for (int j = 0; j < 4; j++)
            pk.h[j] = __floats2bfloat162_rn(expf(acc[i][2*j]), expf(acc[i][2*j+1]));
        *(uint4*)dst = pk.u;
    }
}

// ---------------- 7) row sums over bf16 E -> 1/sum ----------------
__global__ __launch_bounds__(256) void k_rowsum() {
    size_t row = blockIdx.x;
    const uint4* p = (const uint4*)(g_Eh + row * HWN);   // 512 uint4 per row
    float s = 0.f;
    for (int i = threadIdx.x; i < HWN/8; i += 256) {
        uint4 v = p[i];
        union { unsigned int u; __nv_bfloat162 h; } c;
        float2 f;
        c.u = v.x; f = __bfloat1622float2(c.h); s += f.x + f.y;
        c.u = v.y; f = __bfloat1622float2(c.h); s += f.x + f.y;
        c.u = v.z; f = __bfloat1622float2(c.h); s += f.x + f.y;
        c.u = v.w; f = __bfloat1622float2(c.h); s += f.x + f.y;
    }
    __shared__ float ss[8];
    for (int o = 16; o; o >>= 1) s += __shfl_xor_sync(0xffffffffu, s, o);
    if ((threadIdx.x & 31) == 0) ss[threadIdx.x >> 5] = s;
    __syncthreads();
    if (threadIdx.x == 0) {
        float S = 0.f;
        for (int w = 0; w < 8; w++) S += ss[w];
        g_inv[row] = 1.f / S;
    }
}

// ---------------- 8) AV GEMM bf16 tensor-core + epilogue ----------------
// Out[c][i] = sum_j V[c][j] * E[i][j]; tile 128x128 (c x i), K=32 chunks,
// 8 warps (2x4), warp tile 64x32, mma.sync m16n8k16 bf16.
__global__ __launch_bounds__(256) void k_av(const float* __restrict__ gamma,
                                            float* __restrict__ out) {
    int b  = blockIdx.z;
    int c0 = blockIdx.y * 128;
    int i0 = blockIdx.x * 128;
    __shared__ __nv_bfloat16 As[2][128][40];   // [buf][c][k]  80B row stride (conflict-free ldmatrix)
    __shared__ __nv_bfloat16 Bs[2][128][40];   // [buf][i][k]

    int tid = threadIdx.x, lane = tid & 31, wid = tid >> 5;
    int wm = wid >> 2, wn = wid & 3;           // warp tile: rows wm*64, cols wn*32

    const __nv_bfloat16* Vb = g_vh + (size_t)(b*CC + c0) * HWN;
    const __nv_bfloat16* Eb = g_Eh + ((size_t)(b*HWN) + i0) * HWN;

    int lr = tid >> 2;            // 0..63
    int lc = (tid & 3) * 8;       // elem col: 0,8,16,24

    float acc[4][4][4];
    #pragma unroll
    for (int mi = 0; mi < 4; mi++)
        #pragma unroll
        for (int ni = 0; ni < 4; ni++)
            #pragma unroll
            for (int e = 0; e < 4; e++) acc[mi][ni][e] = 0.f;

    // prologue: chunks 0, 1
    #pragma unroll
    for (int pc = 0; pc < 2; pc++) {
        int k0 = pc * 32;
        CP16(&As[pc][lr     ][lc], Vb + (size_t)(lr     )*HWN + k0 + lc);
        CP16(&As[pc][lr + 64][lc], Vb + (size_t)(lr + 64)*HWN + k0 + lc);
        CP16(&Bs[pc][lr     ][lc], Eb + (size_t)(lr     )*HWN + k0 + lc);
        CP16(&Bs[pc][lr + 64][lc], Eb + (size_t)(lr + 64)*HWN + k0 + lc);
        CP_COMMIT();
    }

    #pragma unroll 1
    for (int it = 0; it < 128; it++) {
        int buf = it & 1;
        if (it == 127) { CP_WAIT(0); } else { CP_WAIT(1); }
        __syncthreads();

        #pragma unroll
        for (int ks = 0; ks < 2; ks++) {
            int k = ks * 16;
            int frow = lane & 15;
            int fcol = k + ((lane >> 4) << 3);
            uint32_t a[4][4];
            #pragma unroll
            for (int mi = 0; mi < 4; mi++) {
                unsigned int ad = sptr(&As[buf][wm*64 + mi*16 + frow][fcol]);
                LDSM4(a[mi][0], a[mi][1], a[mi][2], a[mi][3], ad);
            }
            uint32_t bf[2][4];
            #pragma unroll
            for (int nj = 0; nj < 2; nj++) {
                unsigned int ad = sptr(&Bs[buf][wn*32 + nj*16 + frow][fcol]);
                LDSM4(bf[nj][0], bf[nj][1], bf[nj][2], bf[nj][3], ad);
            }
            #pragma unroll
            for (int mi = 0; mi < 4; mi++)
                #pragma unroll
                for (int ni = 0; ni < 4; ni++) {
                    int nj = ni >> 1, h = ni & 1;
                    MMA16816(acc[mi][ni], a[mi], bf[nj][h], bf[nj][h+2]);
                }
        }
        __syncthreads();

        if (it + 2 < 128) {
            int k0 = (it + 2) * 32;
            CP16(&As[buf][lr     ][lc], Vb + (size_t)(lr     )*HWN + k0 + lc);
            CP16(&As[buf][lr + 64][lc], Vb + (size_t)(lr + 64)*HWN + k0 + lc);
            CP16(&Bs[buf][lr     ][lc], Eb + (size_t)(lr     )*HWN + k0 + lc);
            CP16(&Bs[buf][lr + 64][lc], Eb + (size_t)(lr + 64)*HWN + k0 + lc);
            CP_COMMIT();
        }
    }

    // epilogue: out = gamma * acc * inv[i] + xg
    float gm = gamma[0];
    int qr = lane >> 2, qc = (lane & 3) * 2;
    #pragma unroll
    for (int ni = 0; ni < 4; ni++) {
        int icol = i0 + wn*32 + ni*8 + qc;
        float inv0 = g_inv[b*HWN + icol];
        float inv1 = g_inv[b*HWN + icol + 1];
        #pragma unroll
        for (int mi = 0; mi < 4; mi++) {
            int r0 = c0 + wm*64 + mi*16 + qr;
            #pragma unroll
            for (int h = 0; h < 2; h++) {
                int r = r0 + h*8;
                size_t base = ((size_t)(b*CC + r)) * HWN + icol;
                float2 xgv = *(const float2*)(g_xg + base);
                float2 o;
                o.x = gm * acc[mi][ni][2*h+0] * inv0 + xgv.x;
                o.y = gm * acc[mi][ni][2*h+1] * inv1 + xgv.y;
                *(float2*)(out + base) = o;
            }
        }
    }
}

// ---------------- launch ----------------
extern "C" void kernel_launch(void* const* d_in, const int* in_sizes, int n_in,
                              void* d_out, int out_size) {
    const float* x     = (const float*)d_in[0];
    const float* ca_w1 = (const float*)d_in[1];
    const float* ca_w2 = (const float*)d_in[2];
    const float* q_w   = (const float*)d_in[3];
    const float* q_b   = (const float*)d_in[4];
    const float* k_w   = (const float*)d_in[5];
    const float* k_b   = (const float*)d_in[6];
    const float* v_w   = (const float*)d_in[7];
    const float* v_b   = (const float*)d_in[8];
    const float* gamma = (const float*)d_in[9];
    float* out = (float*)d_out;

    k_pool  <<<BB*CC, 256>>>(x);
    k_wpack <<<MQKV, 256>>>(v_w, q_w, k_w, v_b, q_b, k_b);
    k_gate  <<<BB, 256>>>(ca_w1, ca_w2);
    k_xg    <<<(BB*CC*HWN/4)/256, 256>>>(x);
    k_qkv   <<<dim3(HWN/128, 3, BB), 256>>>();
    k_scores<<<dim3(HWN/128, HWN/128, BB), 256>>>();
    k_rowsum<<<BB*HWN, 256>>>();
    k_av    <<<dim3(HWN/128, CC/128, BB), 256>>>(gamma, out);
}

// round 8
// speedup vs baseline: 4.8418x; 1.5023x over previous
#include <cuda_runtime.h>
#include <cuda_bf16.h>
#include <cstdint>
#include <math.h>

#define BB 8
#define CC 256
#define HWN 4096
#define RR 16
#define MQKV 288   // 256 v rows + 16 q rows + 16 k rows
#define MPAD 384   // padded to 3 tiles of 128

// ---------------- scratch (device globals; no allocations) ----------------
__device__ float g_avg[BB*CC];
__device__ float g_mx [BB*CC];
__device__ float g_gate[BB*CC];
__device__ float g_xg[(size_t)BB*CC*HWN];             // fp32 gated input (residual)
__device__ __nv_bfloat16 g_xgt[(size_t)BB*HWN*CC];    // bf16 gated input, transposed [b][n][c]
__device__ __nv_bfloat16 g_wh[MPAD*CC];               // packed bf16 [v;q;k;pad] weights
__device__ float g_bcat[MPAD];
__device__ __nv_bfloat16 g_qt[(size_t)BB*HWN*RR];     // q transposed [b][n][r]
__device__ __nv_bfloat16 g_kt[(size_t)BB*HWN*RR];
__device__ __nv_bfloat16 g_vh[(size_t)BB*CC*HWN];     // V bf16 [b][c][n]
__device__ __nv_bfloat16 g_Eh[(size_t)134217728];     // 256 MB exp(S) bf16 [b][i][j]
__device__ float g_psum[(size_t)BB*HWN*32];           // per-(row, j-tile) partial sums
__device__ float g_inv[BB*HWN];                       // 1/rowsum

// ---------------- asm helpers ----------------
__device__ __forceinline__ unsigned int sptr(const void* p) {
    return (unsigned int)__cvta_generic_to_shared(p);
}
#define CP16(dst, src) asm volatile("cp.async.cg.shared.global [%0], [%1], 16;\n" :: "r"(sptr(dst)), "l"(src))
#define CP_COMMIT()    asm volatile("cp.async.commit_group;\n")
#define CP_WAIT(n)     asm volatile("cp.async.wait_group %0;\n" :: "n"(n))
#define LDSM4(r0,r1,r2,r3,addr) \
    asm volatile("ldmatrix.sync.aligned.m8n8.x4.shared.b16 {%0,%1,%2,%3}, [%4];\n" \
        : "=r"(r0),"=r"(r1),"=r"(r2),"=r"(r3) : "r"(addr))
#define MMA16816(d,a,b0,b1) \
    asm volatile("mma.sync.aligned.m16n8k16.row.col.f32.bf16.bf16.f32 " \
        "{%0,%1,%2,%3}, {%4,%5,%6,%7}, {%8,%9}, {%0,%1,%2,%3};\n" \
        : "+f"(d[0]),"+f"(d[1]),"+f"(d[2]),"+f"(d[3]) \
        : "r"(a[0]),"r"(a[1]),"r"(a[2]),"r"(a[3]), "r"(b0),"r"(b1))

// ---------------- 1) avg+max pool over HW per (b,c) ----------------
__global__ __launch_bounds__(256) void k_pool(const float* __restrict__ x) {
    int bc = blockIdx.x;
    const float4* p = (const float4*)(x + (size_t)bc * HWN);
    float s = 0.f, m = -1e30f;
    for (int i = threadIdx.x; i < HWN/4; i += 256) {
        float4 v = p[i];
        s += v.x + v.y + v.z + v.w;
        m = fmaxf(m, fmaxf(fmaxf(v.x, v.y), fmaxf(v.z, v.w)));
    }
    __shared__ float ss[8], sm[8];
    for (int o = 16; o; o >>= 1) {
        s += __shfl_xor_sync(0xffffffffu, s, o);
        m = fmaxf(m, __shfl_xor_sync(0xffffffffu, m, o));
    }
    if ((threadIdx.x & 31) == 0) { ss[threadIdx.x >> 5] = s; sm[threadIdx.x >> 5] = m; }
    __syncthreads();
    if (threadIdx.x == 0) {
        float S = 0.f, M = -1e30f;
        for (int w = 0; w < 8; w++) { S += ss[w]; M = fmaxf(M, sm[w]); }
        g_avg[bc] = S * (1.f / HWN);
        g_mx[bc]  = M;
    }
}

// ---------------- 2) SE gate ----------------
__global__ __launch_bounds__(256) void k_gate(const float* __restrict__ w1,
                                              const float* __restrict__ w2) {
    int b = blockIdx.x, t = threadIdx.x;
    __shared__ float sa[CC], sx[CC], h[RR];
    sa[t] = g_avg[b*CC + t];
    sx[t] = g_mx [b*CC + t];
    __syncthreads();
    if (t < RR) {
        float da = 0.f, dm = 0.f;
        const float* w = w1 + t*CC;
        for (int c = 0; c < CC; c++) { da += w[c]*sa[c]; dm += w[c]*sx[c]; }
        h[t] = fmaxf(da, 0.f) + fmaxf(dm, 0.f);
    }
    __syncthreads();
    float g = 0.f;
    const float* w = w2 + t*RR;
    #pragma unroll
    for (int r = 0; r < RR; r++) g += w[r]*h[r];
    g_gate[b*CC + t] = 1.f / (1.f + __expf(-g));
}

// ---------------- 3) pack [v;q;k] weights -> bf16 (padded), biases fp32 ----------------
__global__ __launch_bounds__(256) void k_wpack(const float* __restrict__ vw,
                                               const float* __restrict__ qw,
                                               const float* __restrict__ kw,
                                               const float* __restrict__ vb,
                                               const float* __restrict__ qb,
                                               const float* __restrict__ kb) {
    int o = blockIdx.x, t = threadIdx.x;
    float val = 0.f, bias = 0.f;
    if (o < CC)            { val = vw[o*CC + t];          bias = vb[o]; }
    else if (o < CC + RR)  { val = qw[(o-CC)*CC + t];     bias = qb[o-CC]; }
    else if (o < MQKV)     { val = kw[(o-CC-RR)*CC + t];  bias = kb[o-CC-RR]; }
    g_wh[o*CC + t] = __float2bfloat16(val);
    if (t == 0) g_bcat[o] = bias;
}

// ---------------- 4) xg (fp32) + transposed bf16 xgt ----------------
// grid (HWN/32, CC/32, BB), 256 threads
__global__ __launch_bounds__(256) void k_xgt(const float* __restrict__ x) {
    int b = blockIdx.z, c0 = blockIdx.y*32, n0 = blockIdx.x*32;
    __shared__ float t[32][33];
    int tid = threadIdx.x;
    int tx = tid & 31, ty = tid >> 5;        // ty 0..7
    const float* xb  = x    + ((size_t)(b*CC + c0))*HWN + n0;
    float*       xgb = g_xg + ((size_t)(b*CC + c0))*HWN + n0;
    #pragma unroll
    for (int r = ty; r < 32; r += 8) {
        float g = g_gate[b*CC + c0 + r];
        float v = xb[(size_t)r*HWN + tx] * g;
        xgb[(size_t)r*HWN + tx] = v;
        t[r][tx] = v;
    }
    __syncthreads();
    // write g_xgt[b][n][c]
    __nv_bfloat16* dst = g_xgt + ((size_t)(b*HWN + n0))*CC + c0;
    int r2 = tid >> 3, ch = (tid & 7) * 4;   // r2: n-row 0..31, ch: c chunk of 4
    union { __nv_bfloat162 h[2]; uint2 u; } pk;
    pk.h[0] = __floats2bfloat162_rn(t[ch+0][r2], t[ch+1][r2]);
    pk.h[1] = __floats2bfloat162_rn(t[ch+2][r2], t[ch+3][r2]);
    *(uint2*)(dst + (size_t)r2*CC + ch) = pk.u;
}

// ---------------- 5) fused QKV projection, bf16 mma: [384 x 256] @ xgt^T ----------------
// Out[o][n] = sum_c W[o][c] * xgt[n][c]; tile 128x128, K=256 in 8 chunks of 32
__global__ __launch_bounds__(256) void k_qkv() {
    int b  = blockIdx.z;
    int o0 = blockIdx.y * 128;
    int n0 = blockIdx.x * 128;
    __shared__ __align__(16) __nv_bfloat16 As[2][128][40];
    __shared__ __align__(16) __nv_bfloat16 Bs[2][128][40];

    int tid = threadIdx.x, lane = tid & 31, wid = tid >> 5;
    int wm = wid >> 2, wn = wid & 3;

    const __nv_bfloat16* Ab = g_wh + (size_t)o0 * CC;
    const __nv_bfloat16* Bb = g_xgt + ((size_t)(b*HWN) + n0) * CC;

    int lr = tid >> 2;
    int lc = (tid & 3) * 8;

    float acc[4][4][4];
    #pragma unroll
    for (int mi = 0; mi < 4; mi++)
        #pragma unroll
        for (int ni = 0; ni < 4; ni++)
            #pragma unroll
            for (int e = 0; e < 4; e++) acc[mi][ni][e] = 0.f;

    #pragma unroll
    for (int pc = 0; pc < 2; pc++) {
        int k0 = pc * 32;
        CP16(&As[pc][lr     ][lc], Ab + (size_t)(lr     )*CC + k0 + lc);
        CP16(&As[pc][lr + 64][lc], Ab + (size_t)(lr + 64)*CC + k0 + lc);
        CP16(&Bs[pc][lr     ][lc], Bb + (size_t)(lr     )*CC + k0 + lc);
        CP16(&Bs[pc][lr + 64][lc], Bb + (size_t)(lr + 64)*CC + k0 + lc);
        CP_COMMIT();
    }

    #pragma unroll 1
    for (int it = 0; it < 8; it++) {
        int buf = it & 1;
        if (it == 7) { CP_WAIT(0); } else { CP_WAIT(1); }
        __syncthreads();
        #pragma unroll
        for (int ks = 0; ks < 2; ks++) {
            int k = ks * 16;
            int frow = lane & 15;
            int fcol = k + ((lane >> 4) << 3);
            uint32_t a[4][4];
            #pragma unroll
            for (int mi = 0; mi < 4; mi++) {
                unsigned int ad = sptr(&As[buf][wm*64 + mi*16 + frow][fcol]);
                LDSM4(a[mi][0], a[mi][1], a[mi][2], a[mi][3], ad);
            }
            uint32_t bf[2][4];
            #pragma unroll
            for (int nj = 0; nj < 2; nj++) {
                unsigned int ad = sptr(&Bs[buf][wn*32 + nj*16 + frow][fcol]);
                LDSM4(bf[nj][0], bf[nj][1], bf[nj][2], bf[nj][3], ad);
            }
            #pragma unroll
            for (int mi = 0; mi < 4; mi++)
                #pragma unroll
                for (int ni = 0; ni < 4; ni++) {
                    int nj = ni >> 1, h = ni & 1;
                    MMA16816(acc[mi][ni], a[mi], bf[nj][h], bf[nj][h+2]);
                }
        }
        __syncthreads();
        if (it + 2 < 8) {
            int k0 = (it + 2) * 32;
            CP16(&As[buf][lr     ][lc], Ab + (size_t)(lr     )*CC + k0 + lc);
            CP16(&As[buf][lr + 64][lc], Ab + (size_t)(lr + 64)*CC + k0 + lc);
            CP16(&Bs[buf][lr     ][lc], Bb + (size_t)(lr     )*CC + k0 + lc);
            CP16(&Bs[buf][lr + 64][lc], Bb + (size_t)(lr + 64)*CC + k0 + lc);
            CP_COMMIT();
        }
    }

    // epilogue: V rows -> g_vh [c][n] bf16; q/k rows -> transposed g_qt/g_kt [n][r] bf16
    int qr = lane >> 2, qc = (lane & 3) * 2;
    #pragma unroll
    for (int mi = 0; mi < 4; mi++) {
        #pragma unroll
        for (int h = 0; h < 2; h++) {
            int r = o0 + wm*64 + mi*16 + qr + h*8;
            if (r >= MQKV) continue;
            float bias = g_bcat[r];
            if (r < CC) {
                __nv_bfloat16* dst = g_vh + ((size_t)(b*CC + r)) * HWN;
                #pragma unroll
                for (int ni = 0; ni < 4; ni++) {
                    int icol = n0 + wn*32 + ni*8 + qc;
                    *(__nv_bfloat162*)(dst + icol) =
                        __floats2bfloat162_rn(acc[mi][ni][2*h+0] + bias,
                                              acc[mi][ni][2*h+1] + bias);
                }
            } else {
                __nv_bfloat16* dst = (r < CC + RR) ? g_qt : g_kt;
                int rr = (r < CC + RR) ? (r - CC) : (r - CC - RR);
                #pragma unroll
                for (int ni = 0; ni < 4; ni++) {
                    int icol = n0 + wn*32 + ni*8 + qc;
                    dst[((size_t)(b*HWN) + icol    )*RR + rr] = __float2bfloat16(acc[mi][ni][2*h+0] + bias);
                    dst[((size_t)(b*HWN) + icol + 1)*RR + rr] = __float2bfloat16(acc[mi][ni][2*h+1] + bias);
                }
            }
        }
    }
}

// ---------------- 6) scores bf16 mma (K=16) + __expf + staged E write + partial row sums ----------------
__global__ __launch_bounds__(256) void k_scores() {
    int b  = blockIdx.z;
    int i0 = blockIdx.y * 128;
    int j0 = blockIdx.x * 128;
    __shared__ __align__(16) __nv_bfloat16 Qs[128][24];    // 48B rows
    __shared__ __align__(16) __nv_bfloat16 Ks[128][24];
    __shared__ __align__(16) __nv_bfloat16 Es[128][136];   // 272B rows (16B-aligned)
    __shared__ float wsum[2][4][64];

    int tid = threadIdx.x, lane = tid & 31, wid = tid >> 5;
    int wm = wid >> 2, wn = wid & 3;

    {
        int row = tid >> 1, half = tid & 1;
        *(uint4*)&Qs[row][half*8] = *(const uint4*)(g_qt + ((size_t)(b*HWN) + i0 + row)*RR + half*8);
        *(uint4*)&Ks[row][half*8] = *(const uint4*)(g_kt + ((size_t)(b*HWN) + j0 + row)*RR + half*8);
    }
    __syncthreads();

    float acc[4][4][4];
    #pragma unroll
    for (int mi = 0; mi < 4; mi++)
        #pragma unroll
        for (int ni = 0; ni < 4; ni++)
            #pragma unroll
            for (int e = 0; e < 4; e++) acc[mi][ni][e] = 0.f;

    {
        int frow = lane & 15;
        int fcol = (lane >> 4) << 3;
        uint32_t a[4][4];
        #pragma unroll
        for (int mi = 0; mi < 4; mi++) {
            unsigned int ad = sptr(&Qs[wm*64 + mi*16 + frow][fcol]);
            LDSM4(a[mi][0], a[mi][1], a[mi][2], a[mi][3], ad);
        }
        uint32_t bf[2][4];
        #pragma unroll
        for (int nj = 0; nj < 2; nj++) {
            unsigned int ad = sptr(&Ks[wn*32 + nj*16 + frow][fcol]);
            LDSM4(bf[nj][0], bf[nj][1], bf[nj][2], bf[nj][3], ad);
        }
        #pragma unroll
        for (int mi = 0; mi < 4; mi++)
            #pragma unroll
            for (int ni = 0; ni < 4; ni++) {
                int nj = ni >> 1, h = ni & 1;
                MMA16816(acc[mi][ni], a[mi], bf[nj][h], bf[nj][h+2]);
            }
    }

    // exp + stage to smem + per-thread row partials (over bf16-rounded values)
    int qr = lane >> 2, qc = (lane & 3) * 2;
    float ps[8];
    #pragma unroll
    for (int i = 0; i < 8; i++) ps[i] = 0.f;
    #pragma unroll
    for (int mi = 0; mi < 4; mi++) {
        #pragma unroll
        for (int ni = 0; ni < 4; ni++) {
            int col = wn*32 + ni*8 + qc;
            int row = wm*64 + mi*16 + qr;
            __nv_bfloat162 p01 = __floats2bfloat162_rn(__expf(acc[mi][ni][0]), __expf(acc[mi][ni][1]));
            __nv_bfloat162 p23 = __floats2bfloat162_rn(__expf(acc[mi][ni][2]), __expf(acc[mi][ni][3]));
            *(__nv_bfloat162*)&Es[row    ][col] = p01;
            *(__nv_bfloat162*)&Es[row + 8][col] = p23;
            float2 f01 = __bfloat1622float2(p01);
            float2 f23 = __bfloat1622float2(p23);
            ps[mi*2+0] += f01.x + f01.y;
            ps[mi*2+1] += f23.x + f23.y;
        }
    }
    #pragma unroll
    for (int i = 0; i < 8; i++) {
        ps[i] += __shfl_xor_sync(0xffffffffu, ps[i], 1);
        ps[i] += __shfl_xor_sync(0xffffffffu, ps[i], 2);
    }
    if ((lane & 3) == 0) {
        #pragma unroll
        for (int mi = 0; mi < 4; mi++) {
            wsum[wm][wn][mi*16 + qr    ] = ps[mi*2+0];
            wsum[wm][wn][mi*16 + qr + 8] = ps[mi*2+1];
        }
    }
    __syncthreads();

    if (tid < 128) {
        int wmv = tid >> 6, r = tid & 63;
        float s = wsum[wmv][0][r] + wsum[wmv][1][r] + wsum[wmv][2][r] + wsum[wmv][3][r];
        g_psum[((size_t)(b*HWN) + i0 + wmv*64 + r)*32 + blockIdx.x] = s;
    }

    // coalesced E writeout: half-warp per row (256B rows)
    {
        int c16 = tid & 15;            // uint4 index within row
        #pragma unroll 1
        for (int r = tid >> 4; r < 128; r += 16) {
            *(uint4*)(g_Eh + ((size_t)(b*HWN) + i0 + r)*HWN + j0 + c16*8) =
                *(const uint4*)&Es[r][c16*8];
        }
    }
}

// ---------------- 7) reduce partials -> 1/rowsum ----------------
__global__ __launch_bounds__(256) void k_rsum() {
    int row = blockIdx.x * 256 + threadIdx.x;
    const float* p = g_psum + (size_t)row * 32;
    float s = 0.f;
    #pragma unroll
    for (int l = 0; l < 32; l++) s += p[l];
    g_inv[row] = 1.f / s;
}

// ---------------- 8) AV GEMM bf16 tensor-core + epilogue ----------------
__global__ __launch_bounds__(256) void k_av(const float* __restrict__ gamma,
                                            float* __restrict__ out) {
    int b  = blockIdx.z;
    int c0 = blockIdx.y * 128;
    int i0 = blockIdx.x * 128;
    __shared__ __align__(16) __nv_bfloat16 As[2][128][40];
    __shared__ __align__(16) __nv_bfloat16 Bs[2][128][40];

    int tid = threadIdx.x, lane = tid & 31, wid = tid >> 5;
    int wm = wid >> 2, wn = wid & 3;

    const __nv_bfloat16* Vb = g_vh + (size_t)(b*CC + c0) * HWN;
    const __nv_bfloat16* Eb = g_Eh + ((size_t)(b*HWN) + i0) * HWN;

    int lr = tid >> 2;
    int lc = (tid & 3) * 8;

    float acc[4][4][4];
    #pragma unroll
    for (int mi = 0; mi < 4; mi++)
        #pragma unroll
        for (int ni = 0; ni < 4; ni++)
            #pragma unroll
            for (int e = 0; e < 4; e++) acc[mi][ni][e] = 0.f;

    #pragma unroll
    for (int pc = 0; pc < 2; pc++) {
        int k0 = pc * 32;
        CP16(&As[pc][lr     ][lc], Vb + (size_t)(lr     )*HWN + k0 + lc);
        CP16(&As[pc][lr + 64][lc], Vb + (size_t)(lr + 64)*HWN + k0 + lc);
        CP16(&Bs[pc][lr     ][lc], Eb + (size_t)(lr     )*HWN + k0 + lc);
        CP16(&Bs[pc][lr + 64][lc], Eb + (size_t)(lr + 64)*HWN + k0 + lc);
        CP_COMMIT();
    }

    #pragma unroll 1
    for (int it = 0; it < 128; it++) {
        int buf = it & 1;
        if (it == 127) { CP_WAIT(0); } else { CP_WAIT(1); }
        __syncthreads();
        #pragma unroll
        for (int ks = 0; ks < 2; ks++) {
            int k = ks * 16;
            int frow = lane & 15;
            int fcol = k + ((lane >> 4) << 3);
            uint32_t a[4][4];
            #pragma unroll
            for (int mi = 0; mi < 4; mi++) {
                unsigned int ad = sptr(&As[buf][wm*64 + mi*16 + frow][fcol]);
                LDSM4(a[mi][0], a[mi][1], a[mi][2], a[mi][3], ad);
            }
            uint32_t bf[2][4];
            #pragma unroll
            for (int nj = 0; nj < 2; nj++) {
                unsigned int ad = sptr(&Bs[buf][wn*32 + nj*16 + frow][fcol]);
                LDSM4(bf[nj][0], bf[nj][1], bf[nj][2], bf[nj][3], ad);
            }
            #pragma unroll
            for (int mi = 0; mi < 4; mi++)
                #pragma unroll
                for (int ni = 0; ni < 4; ni++) {
                    int nj = ni >> 1, h = ni & 1;
                    MMA16816(acc[mi][ni], a[mi], bf[nj][h], bf[nj][h+2]);
                }
        }
        __syncthreads();
        if (it + 2 < 128) {
            int k0 = (it + 2) * 32;
            CP16(&As[buf][lr     ][lc], Vb + (size_t)(lr     )*HWN + k0 + lc);
            CP16(&As[buf][lr + 64][lc], Vb + (size_t)(lr + 64)*HWN + k0 + lc);
            CP16(&Bs[buf][lr     ][lc], Eb + (size_t)(lr     )*HWN + k0 + lc);
            CP16(&Bs[buf][lr + 64][lc], Eb + (size_t)(lr + 64)*HWN + k0 + lc);
            CP_COMMIT();
        }
    }

    float gm = gamma[0];
    int qr = lane >> 2, qc = (lane & 3) * 2;
    #pragma unroll
    for (int ni = 0; ni < 4; ni++) {
        int icol = i0 + wn*32 + ni*8 + qc;
        float inv0 = g_inv[b*HWN + icol];
        float inv1 = g_inv[b*HWN + icol + 1];
        #pragma unroll
        for (int mi = 0; mi < 4; mi++) {
            int r0 = c0 + wm*64 + mi*16 + qr;
            #pragma unroll
            for (int h = 0; h < 2; h++) {
                int r = r0 + h*8;
                size_t base = ((size_t)(b*CC + r)) * HWN + icol;
                float2 xgv = *(const float2*)(g_xg + base);
                float2 o;
                o.x = gm * acc[mi][ni][2*h+0] * inv0 + xgv.x;
                o.y = gm * acc[mi][ni][2*h+1] * inv1 + xgv.y;
                *(float2*)(out + base) = o;
            }
        }
    }
}

// ---------------- launch ----------------
extern "C" void kernel_launch(void* const* d_in, const int* in_sizes, int n_in,
                              void* d_out, int out_size) {
    const float* x     = (const float*)d_in[0];
    const float* ca_w1 = (const float*)d_in[1];
    const float* ca_w2 = (const float*)d_in[2];
    const float* q_w   = (const float*)d_in[3];
    const float* q_b   = (const float*)d_in[4];
    const float* k_w   = (const float*)d_in[5];
    const float* k_b   = (const float*)d_in[6];
    const float* v_w   = (const float*)d_in[7];
    const float* v_b   = (const float*)d_in[8];
    const float* gamma = (const float*)d_in[9];
    float* out = (float*)d_out;

    k_pool  <<<BB*CC, 256>>>(x);
    k_wpack <<<MPAD, 256>>>(v_w, q_w, k_w, v_b, q_b, k_b);
    k_gate  <<<BB, 256>>>(ca_w1, ca_w2);
    k_xgt   <<<dim3(HWN/32, CC/32, BB), 256>>>(x);
    k_qkv   <<<dim3(HWN/128, MPAD/128, BB), 256>>>();
    k_scores<<<dim3(HWN/128, HWN/128, BB), 256>>>();
    k_rsum  <<<BB*HWN/256, 256>>>();
    k_av    <<<dim3(HWN/128, CC/128, BB), 256>>>(gamma, out);
}